// round 16
// baseline (speedup 1.0000x reference)
#include <cuda_runtime.h>
#include <cuda_fp16.h>
#include <math.h>
#include <stdint.h>

// ---------------- Problem constants ----------------
#define BB 2
#define SS 1024
#define DD 768
#define HH 12
#define HD 64
#define LL 4
#define VV 50257
#define BSr (BB*SS)          // 2048
#define D3 (3*DD)            // 2304
#define D4 (4*DD)            // 3072
#define BH (BB*HH)           // 24

// Half weight scratch offsets (elements). All stored [N,K] (K-contiguous).
#define OFF_ATTN 0
#define N_ATTN   (LL*DD*D3)
#define OFF_PROJ (OFF_ATTN + N_ATTN)
#define N_PROJ   (LL*DD*DD)
#define OFF_FC   (OFF_PROJ + N_PROJ)
#define N_FC     (LL*DD*D4)
#define OFF_FC2  (OFF_FC + N_FC)
#define N_FC2    (LL*D4*DD)
#define OFF_WTE  (OFF_FC2 + N_FC2)
#define N_WTE    (VV*DD)
#define N_WH     (OFF_WTE + N_WTE)

// ---------------- Scratch (device globals) ----------------
__device__ float  g_h[BSr*DD];
__device__ __half g_xln[BSr*DD];
__device__ __half g_qkv[BSr*D3];
__device__ __half g_abuf[BSr*DD];
__device__ __half g_fc[BSr*D4];
__device__ __half g_wh[N_WH];

// ---------------- Helpers ----------------
__device__ __forceinline__ float gelu_f(float x) {
    const float c = 0.7978845608028654f;
    float t = tanhf(c * (x + 0.044715f * x * x * x));
    return 0.5f * x * (1.0f + t);
}
__device__ __forceinline__ void mma_f16(float* c, const uint32_t* a, uint32_t b0, uint32_t b1) {
    asm volatile(
        "mma.sync.aligned.m16n8k16.row.col.f32.f16.f16.f32 "
        "{%0,%1,%2,%3}, {%4,%5,%6,%7}, {%8,%9}, {%0,%1,%2,%3};\n"
        : "+f"(c[0]), "+f"(c[1]), "+f"(c[2]), "+f"(c[3])
        : "r"(a[0]), "r"(a[1]), "r"(a[2]), "r"(a[3]), "r"(b0), "r"(b1));
}
__device__ __forceinline__ uint32_t smem_u32(const void* p) {
    return (uint32_t)__cvta_generic_to_shared(p);
}
__device__ __forceinline__ void cpa16(const void* dst, const void* src, int srcbytes) {
    asm volatile("cp.async.ca.shared.global [%0], [%1], 16, %2;\n"
                 :: "r"(smem_u32(dst)), "l"(src), "r"(srcbytes));
}
__device__ __forceinline__ uint32_t packh2(float a, float b) {
    __half2 h = __floats2half2_rn(a, b);
    return *(uint32_t*)&h;
}
__device__ __forceinline__ void ldsm4(uint32_t* d, uint32_t addr) {
    asm volatile("ldmatrix.sync.aligned.m8n8.x4.shared.b16 {%0,%1,%2,%3}, [%4];"
                 : "=r"(d[0]), "=r"(d[1]), "=r"(d[2]), "=r"(d[3]) : "r"(addr));
}

// ---------------- Weight conversion ----------------
__global__ void trph_kernel(const float* __restrict__ src, __half* __restrict__ dst,
                            int K, int N) {
    __shared__ float t[32][33];
    const float* s = src + (size_t)blockIdx.z * K * N;
    __half* d = dst + (size_t)blockIdx.z * N * K;
    int nb = blockIdx.x * 32, kb = blockIdx.y * 32;
    int tx = threadIdx.x, ty = threadIdx.y;
#pragma unroll
    for (int r = 0; r < 4; r++)
        t[ty + 8 * r][tx] = s[(size_t)(kb + ty + 8 * r) * N + nb + tx];
    __syncthreads();
#pragma unroll
    for (int r = 0; r < 4; r++)
        d[(size_t)(nb + ty + 8 * r) * K + kb + tx] = __float2half_rn(t[tx][ty + 8 * r]);
}

__global__ void convh_kernel(const float* __restrict__ src, __half* __restrict__ dst, int n4) {
    int i = blockIdx.x * blockDim.x + threadIdx.x;
    int stride = gridDim.x * blockDim.x;
    for (; i < n4; i += stride) {
        float4 v = ((const float4*)src)[i];
        ((uint2*)dst)[i] = make_uint2(packh2(v.x, v.y), packh2(v.z, v.w));
    }
}

// ---------------- Embedding ----------------
__global__ void embed_kernel(const int* __restrict__ X, const float* __restrict__ wte,
                             const float* __restrict__ wpe, float* __restrict__ h) {
    int bs = blockIdx.x;
    int s = bs & (SS - 1);
    int tok = X[bs];
    const float* we = wte + (size_t)tok * DD;
    const float* wp = wpe + (size_t)s * DD;
    float* out = h + (size_t)bs * DD;
    int tid = threadIdx.x;
#pragma unroll
    for (int q = 0; q < 3; q++) {
        int d = tid + q * 256;
        out[d] = we[d] + wp[d];
    }
}

// ---------------- LayerNorm: warp per row, 8 rows per block ----------------
__global__ void __launch_bounds__(256) layernorm_kernel(
        const float* __restrict__ in, const float* __restrict__ g,
        const float* __restrict__ b, __half* __restrict__ out) {
    int warp = threadIdx.x >> 5, lane = threadIdx.x & 31;
    int r = blockIdx.x * 8 + warp;
    const float4* x = (const float4*)(in + (size_t)r * DD);
    float4 v[6];
    float s = 0.0f;
#pragma unroll
    for (int i = 0; i < 6; i++) {
        v[i] = x[lane + 32 * i];
        s += v[i].x + v[i].y + v[i].z + v[i].w;
    }
#pragma unroll
    for (int o = 16; o > 0; o >>= 1) s += __shfl_xor_sync(0xffffffffu, s, o);
    float m = s * (1.0f / DD);
    float vs = 0.0f;
#pragma unroll
    for (int i = 0; i < 6; i++) {
        v[i].x -= m; v[i].y -= m; v[i].z -= m; v[i].w -= m;
        vs += v[i].x * v[i].x + v[i].y * v[i].y + v[i].z * v[i].z + v[i].w * v[i].w;
    }
#pragma unroll
    for (int o = 16; o > 0; o >>= 1) vs += __shfl_xor_sync(0xffffffffu, vs, o);
    float inv = rsqrtf(vs * (1.0f / DD) + 1e-5f);
    const float4* g4 = (const float4*)g;
    const float4* b4 = (const float4*)b;
    uint2* o2 = (uint2*)(out + (size_t)r * DD);
#pragma unroll
    for (int i = 0; i < 6; i++) {
        int idx = lane + 32 * i;
        float4 gg = g4[idx], bb = b4[idx];
        float y0 = v[i].x * inv * gg.x + bb.x;
        float y1 = v[i].y * inv * gg.y + bb.y;
        float y2 = v[i].z * inv * gg.z + bb.z;
        float y3 = v[i].w * inv * gg.w + bb.w;
        o2[idx] = make_uint2(packh2(y0, y1), packh2(y2, y3));
    }
}

// ---------------- FP16 tensor-core GEMM (layer GEMMs, proven R8) ----------------
template <int EPI, int TM, bool GUARD, typename OutT>
__global__ void __launch_bounds__(256, 2)
h_gemm(const __half* __restrict__ A, const __half* __restrict__ Bt,
       const float* __restrict__ bias, const float* __restrict__ res,
       OutT* __restrict__ C, int M, int N, int K) {
    constexpr int WR = TM / 32;
    constexpr int WC = 8 / WR;
    constexpr int WN = 128 / WC;
    constexpr int NI = WN / 8;
    constexpr int ASTR = TM * 40;
    constexpr int BSTR = 128 * 40;

    extern __shared__ __half smh[];
    __half* Asm = smh;
    __half* Bsm = smh + 3 * ASTR;

    int tid = threadIdx.x;
    int lane = tid & 31;
    int warp = tid >> 5;
    int gid = lane >> 2, tig = lane & 3;
    int warp_m = warp % WR, warp_n = warp / WR;
    int row0 = blockIdx.x * TM, col0 = blockIdx.y * 128;

    int a_r = (lane & 7) + ((lane >> 3) & 1) * 8;
    int a_c = (lane >> 4) * 8;
    int b_n = (lane & 7) + (lane >> 4) * 8;
    int b_k = ((lane >> 3) & 1) * 8;
    uint32_t Au = smem_u32(Asm), Bu = smem_u32(Bsm);

    float acc[2][NI][4];
#pragma unroll
    for (int mi = 0; mi < 2; mi++)
#pragma unroll
        for (int ni = 0; ni < NI; ni++)
#pragma unroll
            for (int e = 0; e < 4; e++) acc[mi][ni][e] = 0.0f;

    auto stage_fn = [&](int s, int k0) {
        __half* As = Asm + s * ASTR;
        __half* Bs = Bsm + s * BSTR;
#pragma unroll
        for (int q = 0; q < TM / 64; q++) {
            int cid = tid + q * 256;
            int r = cid >> 2, ch = (cid & 3) * 8;
            cpa16(As + r * 40 + ch, A + (size_t)(row0 + r) * K + k0 + ch, 16);
        }
#pragma unroll
        for (int q = 0; q < 2; q++) {
            int cid = tid + q * 256;
            int n = cid >> 2, ch = (cid & 3) * 8;
            bool ok = (!GUARD) || (col0 + n) < N;
            const __half* src = ok ? (Bt + (size_t)(col0 + n) * K + k0 + ch) : Bt;
            cpa16(Bs + n * 40 + ch, src, ok ? 16 : 0);
        }
        asm volatile("cp.async.commit_group;\n");
    };

    auto compute_fn = [&](int s) {
        uint32_t Abase = Au + s * (ASTR * 2);
        uint32_t Bbase = Bu + s * (BSTR * 2);
#pragma unroll
        for (int kk = 0; kk < 2; kk++) {
            int kh = kk * 16;
            uint32_t af[2][4];
#pragma unroll
            for (int mi = 0; mi < 2; mi++) {
                int rb = warp_m * 32 + mi * 16;
                ldsm4(af[mi], Abase + ((rb + a_r) * 40 + kh + a_c) * 2);
            }
            uint32_t bf[NI][2];
#pragma unroll
            for (int j = 0; j < NI / 2; j++) {
                uint32_t d[4];
                ldsm4(d, Bbase + ((warp_n * WN + j * 16 + b_n) * 40 + kh + b_k) * 2);
                bf[2 * j][0] = d[0]; bf[2 * j][1] = d[1];
                bf[2 * j + 1][0] = d[2]; bf[2 * j + 1][1] = d[3];
            }
#pragma unroll
            for (int ni = 0; ni < NI; ni++) {
                mma_f16(acc[0][ni], af[0], bf[ni][0], bf[ni][1]);
                mma_f16(acc[1][ni], af[1], bf[ni][0], bf[ni][1]);
            }
        }
    };

    int nIter = K >> 5;
    stage_fn(0, 0);
    stage_fn(1, 32);
    for (int i = 0; i < nIter; i++) {
        asm volatile("cp.async.wait_group 1;\n");
        __syncthreads();
        if (i + 2 < nIter) stage_fn((i + 2) % 3, (i + 2) << 5);
        else asm volatile("cp.async.commit_group;\n");
        compute_fn(i % 3);
    }

    int row_w = row0 + warp_m * 32;
    int col_w = col0 + warp_n * WN;
#pragma unroll
    for (int mi = 0; mi < 2; mi++) {
        int r0 = row_w + mi * 16 + gid;
        int r1 = r0 + 8;
#pragma unroll
        for (int ni = 0; ni < NI; ni++) {
            int c0 = col_w + ni * 8 + tig * 2;
#pragma unroll
            for (int e = 0; e < 4; e++) {
                int r = (e < 2) ? r0 : r1;
                int c = c0 + (e & 1);
                if (GUARD && c >= N) continue;
                float v = acc[mi][ni][e];
                if (EPI == 0) v = v + bias[c];
                if (EPI == 1) v = gelu_f(v + bias[c]);
                if (EPI == 2) v = v + bias[c] + res[(size_t)r * N + c];
                if (sizeof(OutT) == 2)
                    ((__half*)C)[(size_t)r * N + c] = __float2half_rn(v);
                else
                    ((float*)C)[(size_t)r * N + c] = v;
            }
        }
    }
}

#define SMEMH(TM) (3 * ((TM) + 128) * 40 * 2)

// ---------------- Big-tile GEMM for logits: CTA 128x256, warp 64x64 ----------------
// C[M,N] = A[M,K] @ Bt[N,K]^T, plain epilogue, fp32 out, N guarded.
// 8 warps arranged 2(M) x 4(N); per warp per BK=32: 64 HMMA / 16 LDSM.x4.
// 1 CTA/SM (128 acc regs/thread), 3-stage cp.async, 1 sync/iter.
#define ASTR_BIG (128 * 40)
#define BSTR_BIG (256 * 40)
#define SMEMH_BIG (3 * (ASTR_BIG + BSTR_BIG) * 2)
__global__ void __launch_bounds__(256, 1)
h_gemm_big(const __half* __restrict__ A, const __half* __restrict__ Bt,
           float* __restrict__ C, int M, int N, int K) {
    extern __shared__ __half smh[];
    __half* Asm = smh;
    __half* Bsm = smh + 3 * ASTR_BIG;

    int tid = threadIdx.x;
    int lane = tid & 31;
    int warp = tid >> 5;
    int gid = lane >> 2, tig = lane & 3;
    int warp_m = warp & 1, warp_n = warp >> 1;
    int row0 = blockIdx.x * 128, col0 = blockIdx.y * 256;

    int a_r = (lane & 7) + ((lane >> 3) & 1) * 8;
    int a_c = (lane >> 4) * 8;
    int b_n = (lane & 7) + (lane >> 4) * 8;
    int b_k = ((lane >> 3) & 1) * 8;
    uint32_t Au = smem_u32(Asm), Bu = smem_u32(Bsm);

    float acc[4][8][4];
#pragma unroll
    for (int mi = 0; mi < 4; mi++)
#pragma unroll
        for (int ni = 0; ni < 8; ni++)
#pragma unroll
            for (int e = 0; e < 4; e++) acc[mi][ni][e] = 0.0f;

    auto stage_fn = [&](int s, int k0) {
        __half* As = Asm + s * ASTR_BIG;
        __half* Bs = Bsm + s * BSTR_BIG;
#pragma unroll
        for (int q = 0; q < 2; q++) {
            int cid = tid + q * 256;
            int r = cid >> 2, ch = (cid & 3) * 8;
            cpa16(As + r * 40 + ch, A + (size_t)(row0 + r) * K + k0 + ch, 16);
        }
#pragma unroll
        for (int q = 0; q < 4; q++) {
            int cid = tid + q * 256;
            int n = cid >> 2, ch = (cid & 3) * 8;
            bool ok = (col0 + n) < N;
            const __half* src = ok ? (Bt + (size_t)(col0 + n) * K + k0 + ch) : Bt;
            cpa16(Bs + n * 40 + ch, src, ok ? 16 : 0);
        }
        asm volatile("cp.async.commit_group;\n");
    };

    auto compute_fn = [&](int s) {
        uint32_t Abase = Au + s * (ASTR_BIG * 2);
        uint32_t Bbase = Bu + s * (BSTR_BIG * 2);
#pragma unroll
        for (int kk = 0; kk < 2; kk++) {
            int kh = kk * 16;
            uint32_t af[4][4];
#pragma unroll
            for (int mi = 0; mi < 4; mi++) {
                int rb = warp_m * 64 + mi * 16;
                ldsm4(af[mi], Abase + ((rb + a_r) * 40 + kh + a_c) * 2);
            }
            uint32_t bf[8][2];
#pragma unroll
            for (int j = 0; j < 4; j++) {
                uint32_t d[4];
                ldsm4(d, Bbase + ((warp_n * 64 + j * 16 + b_n) * 40 + kh + b_k) * 2);
                bf[2 * j][0] = d[0]; bf[2 * j][1] = d[1];
                bf[2 * j + 1][0] = d[2]; bf[2 * j + 1][1] = d[3];
            }
#pragma unroll
            for (int mi = 0; mi < 4; mi++)
#pragma unroll
                for (int ni = 0; ni < 8; ni++)
                    mma_f16(acc[mi][ni], af[mi], bf[ni][0], bf[ni][1]);
        }
    };

    int nIter = K >> 5;
    stage_fn(0, 0);
    stage_fn(1, 32);
    for (int i = 0; i < nIter; i++) {
        asm volatile("cp.async.wait_group 1;\n");
        __syncthreads();
        if (i + 2 < nIter) stage_fn((i + 2) % 3, (i + 2) << 5);
        else asm volatile("cp.async.commit_group;\n");
        compute_fn(i % 3);
    }

    int row_w = row0 + warp_m * 64;
    int col_w = col0 + warp_n * 64;
#pragma unroll
    for (int mi = 0; mi < 4; mi++) {
        int r0 = row_w + mi * 16 + gid;
        int r1 = r0 + 8;
#pragma unroll
        for (int ni = 0; ni < 8; ni++) {
            int c0 = col_w + ni * 8 + tig * 2;
#pragma unroll
            for (int e = 0; e < 4; e++) {
                int r = (e < 2) ? r0 : r1;
                int c = c0 + (e & 1);
                if (c < N) C[(size_t)r * N + c] = acc[mi][ni][e];
            }
        }
    }
}

// ---------------- FP16 fused flash attention (proven R7/R8) ----------------
__global__ void __launch_bounds__(128) flash_kernel(const __half* __restrict__ qkv,
                                                    __half* __restrict__ out) {
    int it = blockIdx.x, bh = blockIdx.y;
    int b = bh / HH, h = bh % HH;
    int i0 = it * 64;
    int tid = threadIdx.x, lane = tid & 31, warp = tid >> 5;
    int gid = lane >> 2, tig = lane & 3;

    __shared__ __half Qs[64 * 64];
    __shared__ __half Ks[64 * 64];
    __shared__ __half Vs[64 * 64];

#define SWH(r, c) ((r) * 64 + ((((c) >> 3) ^ ((r) & 7)) * 8) + ((c) & 7))

#pragma unroll
    for (int q = 0; q < 4; q++) {
        int cid = tid + q * 128;
        int r = cid >> 3, c8 = (cid & 7) * 8;
        uint4 v = *(const uint4*)(qkv + (size_t)(b * SS + i0 + r) * D3 + h * HD + c8);
        *(uint4*)&Qs[SWH(r, c8)] = v;
    }
    __syncthreads();

    uint32_t qa[4][4];
    int r0 = warp * 16 + gid;
#pragma unroll
    for (int ks = 0; ks < 4; ks++) {
        int kh = ks * 16;
        qa[ks][0] = *(const uint32_t*)&Qs[SWH(r0,     kh + 2 * tig)];
        qa[ks][1] = *(const uint32_t*)&Qs[SWH(r0 + 8, kh + 2 * tig)];
        qa[ks][2] = *(const uint32_t*)&Qs[SWH(r0,     kh + 8 + 2 * tig)];
        qa[ks][3] = *(const uint32_t*)&Qs[SWH(r0 + 8, kh + 8 + 2 * tig)];
    }

    float oacc[8][4];
#pragma unroll
    for (int nt = 0; nt < 8; nt++)
#pragma unroll
        for (int e = 0; e < 4; e++) oacc[nt][e] = 0.0f;
    float m_run[2] = {-1e30f, -1e30f};
    float l_run[2] = {0.0f, 0.0f};

    for (int j0 = 0; j0 <= i0; j0 += 64) {
        __syncthreads();
#pragma unroll
        for (int q = 0; q < 4; q++) {
            int cid = tid + q * 128;
            int r = cid >> 3, c8 = (cid & 7) * 8;
            const __half* kp = qkv + (size_t)(b * SS + j0 + r) * D3 + DD + h * HD + c8;
            *(uint4*)&Ks[SWH(r, c8)] = *(const uint4*)kp;
            uint4 vv = *(const uint4*)(kp + DD);
            const __half* vh = (const __half*)&vv;
#pragma unroll
            for (int t = 0; t < 8; t++) Vs[SWH(c8 + t, r)] = vh[t];
        }
        __syncthreads();

        float sacc[8][4];
#pragma unroll
        for (int nt = 0; nt < 8; nt++)
#pragma unroll
            for (int e = 0; e < 4; e++) sacc[nt][e] = 0.0f;
#pragma unroll
        for (int ks = 0; ks < 4; ks++) {
            int kh = ks * 16;
#pragma unroll
            for (int nt = 0; nt < 8; nt++) {
                int n0 = nt * 8 + gid;
                uint32_t b0 = *(const uint32_t*)&Ks[SWH(n0, kh + 2 * tig)];
                uint32_t b1 = *(const uint32_t*)&Ks[SWH(n0, kh + 8 + 2 * tig)];
                mma_f16(sacc[nt], qa[ks], b0, b1);
            }
        }

        bool diag = (j0 == i0);
#pragma unroll
        for (int nt = 0; nt < 8; nt++)
#pragma unroll
            for (int e = 0; e < 4; e++) {
                float s = sacc[nt][e] * 0.125f;
                if (diag) {
                    int rr = warp * 16 + gid + (e >> 1) * 8;
                    int cc = nt * 8 + tig * 2 + (e & 1);
                    if (cc > rr) s = -1e10f;
                }
                sacc[nt][e] = s;
            }

        float mloc[2] = {-1e30f, -1e30f};
#pragma unroll
        for (int nt = 0; nt < 8; nt++)
#pragma unroll
            for (int e = 0; e < 4; e++) mloc[e >> 1] = fmaxf(mloc[e >> 1], sacc[nt][e]);
#pragma unroll
        for (int hh = 0; hh < 2; hh++) {
            mloc[hh] = fmaxf(mloc[hh], __shfl_xor_sync(0xffffffffu, mloc[hh], 1));
            mloc[hh] = fmaxf(mloc[hh], __shfl_xor_sync(0xffffffffu, mloc[hh], 2));
        }
        float mnew[2] = {fmaxf(m_run[0], mloc[0]), fmaxf(m_run[1], mloc[1])};
        float al[2] = {__expf(m_run[0] - mnew[0]), __expf(m_run[1] - mnew[1])};

        float psum[2] = {0.0f, 0.0f};
#pragma unroll
        for (int nt = 0; nt < 8; nt++)
#pragma unroll
            for (int e = 0; e < 4; e++) {
                float p = __expf(sacc[nt][e] - mnew[e >> 1]);
                sacc[nt][e] = p;
                psum[e >> 1] += p;
            }
#pragma unroll
        for (int hh = 0; hh < 2; hh++) {
            psum[hh] += __shfl_xor_sync(0xffffffffu, psum[hh], 1);
            psum[hh] += __shfl_xor_sync(0xffffffffu, psum[hh], 2);
            l_run[hh] = l_run[hh] * al[hh] + psum[hh];
            m_run[hh] = mnew[hh];
        }
#pragma unroll
        for (int nt = 0; nt < 8; nt++)
#pragma unroll
            for (int e = 0; e < 4; e++) oacc[nt][e] *= al[e >> 1];

#pragma unroll
        for (int ks = 0; ks < 4; ks++) {
            uint32_t pa[4];
            pa[0] = packh2(sacc[2 * ks][0],     sacc[2 * ks][1]);
            pa[1] = packh2(sacc[2 * ks][2],     sacc[2 * ks][3]);
            pa[2] = packh2(sacc[2 * ks + 1][0], sacc[2 * ks + 1][1]);
            pa[3] = packh2(sacc[2 * ks + 1][2], sacc[2 * ks + 1][3]);
            int kh = ks * 16;
#pragma unroll
            for (int nt = 0; nt < 8; nt++) {
                int n0 = nt * 8 + gid;
                uint32_t b0 = *(const uint32_t*)&Vs[SWH(n0, kh + 2 * tig)];
                uint32_t b1 = *(const uint32_t*)&Vs[SWH(n0, kh + 8 + 2 * tig)];
                mma_f16(oacc[nt], pa, b0, b1);
            }
        }
    }

    float inv[2] = {1.0f / l_run[0], 1.0f / l_run[1]};
#pragma unroll
    for (int nt = 0; nt < 8; nt++)
#pragma unroll
        for (int e = 0; e < 4; e++) {
            int i = i0 + warp * 16 + gid + (e >> 1) * 8;
            int d = nt * 8 + tig * 2 + (e & 1);
            float v = oacc[nt][e] * inv[e >> 1];
            out[(size_t)(b * SS + i) * DD + h * HD + d] = __float2half_rn(v);
        }
#undef SWH
}

// ---------------- Orchestration ----------------
extern "C" void kernel_launch(void* const* d_in, const int* in_sizes, int n_in,
                              void* d_out, int out_size) {
    const int*   X      = (const int*)d_in[0];
    const float* wte    = (const float*)d_in[1];
    const float* wpe    = (const float*)d_in[2];
    const float* ln1_g  = (const float*)d_in[3];
    const float* ln1_b  = (const float*)d_in[4];
    const float* attn_w = (const float*)d_in[5];
    const float* attn_b = (const float*)d_in[6];
    const float* proj_w = (const float*)d_in[7];
    const float* proj_b = (const float*)d_in[8];
    const float* ln2_g  = (const float*)d_in[9];
    const float* ln2_b  = (const float*)d_in[10];
    const float* fc_w   = (const float*)d_in[11];
    const float* fc_b   = (const float*)d_in[12];
    const float* fc2_w  = (const float*)d_in[13];
    const float* fc2_b  = (const float*)d_in[14];
    const float* lnf_g  = (const float*)d_in[15];
    const float* lnf_b  = (const float*)d_in[16];
    float* out = (float*)d_out;

    float* h;
    __half *xln, *qkv, *abuf, *fcb, *wh;
    cudaGetSymbolAddress((void**)&h,    g_h);
    cudaGetSymbolAddress((void**)&xln,  g_xln);
    cudaGetSymbolAddress((void**)&qkv,  g_qkv);
    cudaGetSymbolAddress((void**)&abuf, g_abuf);
    cudaGetSymbolAddress((void**)&fcb,  g_fc);
    cudaGetSymbolAddress((void**)&wh,   g_wh);

    cudaFuncSetAttribute(h_gemm<0, 128, false, __half>,
                         cudaFuncAttributeMaxDynamicSharedMemorySize, SMEMH(128));
    cudaFuncSetAttribute(h_gemm<1, 128, false, __half>,
                         cudaFuncAttributeMaxDynamicSharedMemorySize, SMEMH(128));
    cudaFuncSetAttribute(h_gemm<2, 64, false, float>,
                         cudaFuncAttributeMaxDynamicSharedMemorySize, SMEMH(64));
    cudaFuncSetAttribute(h_gemm_big,
                         cudaFuncAttributeMaxDynamicSharedMemorySize, SMEMH_BIG);

    trph_kernel<<<dim3(D3 / 32, DD / 32, LL), dim3(32, 8)>>>(attn_w, wh + OFF_ATTN, DD, D3);
    trph_kernel<<<dim3(DD / 32, DD / 32, LL), dim3(32, 8)>>>(proj_w, wh + OFF_PROJ, DD, DD);
    trph_kernel<<<dim3(D4 / 32, DD / 32, LL), dim3(32, 8)>>>(fc_w,   wh + OFF_FC,   DD, D4);
    trph_kernel<<<dim3(DD / 32, D4 / 32, LL), dim3(32, 8)>>>(fc2_w,  wh + OFF_FC2,  D4, DD);
    convh_kernel<<<4096, 256>>>(wte, wh + OFF_WTE, N_WTE / 4);

    embed_kernel<<<BSr, 256>>>(X, wte, wpe, h);

    for (int l = 0; l < LL; l++) {
        layernorm_kernel<<<BSr / 8, 256>>>(h, ln1_g + l * DD, ln1_b + l * DD, xln);
        h_gemm<0, 128, false, __half>
            <<<dim3(BSr / 128, D3 / 128), 256, SMEMH(128)>>>(
            xln, wh + OFF_ATTN + (size_t)l * DD * D3, attn_b + (size_t)l * D3, nullptr,
            qkv, BSr, D3, DD);
        flash_kernel<<<dim3(SS / 64, BH), 128>>>(qkv, abuf);
        h_gemm<2, 64, false, float>
            <<<dim3(BSr / 64, DD / 128), 256, SMEMH(64)>>>(
            abuf, wh + OFF_PROJ + (size_t)l * DD * DD, proj_b + (size_t)l * DD, h,
            h, BSr, DD, DD);
        layernorm_kernel<<<BSr / 8, 256>>>(h, ln2_g + l * DD, ln2_b + l * DD, xln);
        h_gemm<1, 128, false, __half>
            <<<dim3(BSr / 128, D4 / 128), 256, SMEMH(128)>>>(
            xln, wh + OFF_FC + (size_t)l * DD * D4, fc_b + (size_t)l * D4, nullptr,
            fcb, BSr, D4, DD);
        h_gemm<2, 64, false, float>
            <<<dim3(BSr / 64, DD / 128), 256, SMEMH(64)>>>(
            fcb, wh + OFF_FC2 + (size_t)l * D4 * DD, fc2_b + (size_t)l * DD, h,
            h, BSr, DD, D4);
    }

    layernorm_kernel<<<BSr / 8, 256>>>(h, lnf_g, lnf_b, xln);
    // Logits: big tile 128x256; grid x = row tiles (16) for 16-way wte L2 reuse
    h_gemm_big<<<dim3(BSr / 128, (VV + 255) / 256), 256, SMEMH_BIG>>>(
        xln, wh + OFF_WTE, out, BSr, VV, DD);
}

// round 17
// speedup vs baseline: 1.1227x; 1.1227x over previous
#include <cuda_runtime.h>
#include <cuda_fp16.h>
#include <math.h>
#include <stdint.h>

// ---------------- Problem constants ----------------
#define BB 2
#define SS 1024
#define DD 768
#define HH 12
#define HD 64
#define LL 4
#define VV 50257
#define BSr (BB*SS)          // 2048
#define D3 (3*DD)            // 2304
#define D4 (4*DD)            // 3072
#define BH (BB*HH)           // 24

// Half weight scratch offsets (elements). All stored [N,K] (K-contiguous).
#define OFF_ATTN 0
#define N_ATTN   (LL*DD*D3)
#define OFF_PROJ (OFF_ATTN + N_ATTN)
#define N_PROJ   (LL*DD*DD)
#define OFF_FC   (OFF_PROJ + N_PROJ)
#define N_FC     (LL*DD*D4)
#define OFF_FC2  (OFF_FC + N_FC)
#define N_FC2    (LL*D4*DD)
#define OFF_WTE  (OFF_FC2 + N_FC2)
#define N_WTE    (VV*DD)
#define N_WH     (OFF_WTE + N_WTE)

// ---------------- Scratch (device globals) ----------------
__device__ float  g_h[BSr*DD];
__device__ __half g_xln[BSr*DD];
__device__ __half g_qkv[BSr*D3];
__device__ __half g_abuf[BSr*DD];
__device__ __half g_fc[BSr*D4];
__device__ __half g_wh[N_WH];

// ---------------- Helpers ----------------
__device__ __forceinline__ float gelu_f(float x) {
    const float c = 0.7978845608028654f;
    float t = tanhf(c * (x + 0.044715f * x * x * x));
    return 0.5f * x * (1.0f + t);
}
__device__ __forceinline__ void mma_f16(float* c, const uint32_t* a, uint32_t b0, uint32_t b1) {
    asm volatile(
        "mma.sync.aligned.m16n8k16.row.col.f32.f16.f16.f32 "
        "{%0,%1,%2,%3}, {%4,%5,%6,%7}, {%8,%9}, {%0,%1,%2,%3};\n"
        : "+f"(c[0]), "+f"(c[1]), "+f"(c[2]), "+f"(c[3])
        : "r"(a[0]), "r"(a[1]), "r"(a[2]), "r"(a[3]), "r"(b0), "r"(b1));
}
__device__ __forceinline__ uint32_t smem_u32(const void* p) {
    return (uint32_t)__cvta_generic_to_shared(p);
}
__device__ __forceinline__ void cpa16(const void* dst, const void* src, int srcbytes) {
    asm volatile("cp.async.ca.shared.global [%0], [%1], 16, %2;\n"
                 :: "r"(smem_u32(dst)), "l"(src), "r"(srcbytes));
}
__device__ __forceinline__ uint32_t packh2(float a, float b) {
    __half2 h = __floats2half2_rn(a, b);
    return *(uint32_t*)&h;
}
__device__ __forceinline__ void ldsm4(uint32_t* d, uint32_t addr) {
    asm volatile("ldmatrix.sync.aligned.m8n8.x4.shared.b16 {%0,%1,%2,%3}, [%4];"
                 : "=r"(d[0]), "=r"(d[1]), "=r"(d[2]), "=r"(d[3]) : "r"(addr));
}
__device__ __forceinline__ void ldsm4t(uint32_t* d, uint32_t addr) {
    asm volatile("ldmatrix.sync.aligned.m8n8.x4.trans.shared.b16 {%0,%1,%2,%3}, [%4];"
                 : "=r"(d[0]), "=r"(d[1]), "=r"(d[2]), "=r"(d[3]) : "r"(addr));
}

// ---------------- Weight conversion ----------------
__global__ void trph_kernel(const float* __restrict__ src, __half* __restrict__ dst,
                            int K, int N) {
    __shared__ float t[32][33];
    const float* s = src + (size_t)blockIdx.z * K * N;
    __half* d = dst + (size_t)blockIdx.z * N * K;
    int nb = blockIdx.x * 32, kb = blockIdx.y * 32;
    int tx = threadIdx.x, ty = threadIdx.y;
#pragma unroll
    for (int r = 0; r < 4; r++)
        t[ty + 8 * r][tx] = s[(size_t)(kb + ty + 8 * r) * N + nb + tx];
    __syncthreads();
#pragma unroll
    for (int r = 0; r < 4; r++)
        d[(size_t)(nb + ty + 8 * r) * K + kb + tx] = __float2half_rn(t[tx][ty + 8 * r]);
}

__global__ void convh_kernel(const float* __restrict__ src, __half* __restrict__ dst, int n4) {
    int i = blockIdx.x * blockDim.x + threadIdx.x;
    int stride = gridDim.x * blockDim.x;
    for (; i < n4; i += stride) {
        float4 v = ((const float4*)src)[i];
        ((uint2*)dst)[i] = make_uint2(packh2(v.x, v.y), packh2(v.z, v.w));
    }
}

// ---------------- Embedding ----------------
__global__ void embed_kernel(const int* __restrict__ X, const float* __restrict__ wte,
                             const float* __restrict__ wpe, float* __restrict__ h) {
    int bs = blockIdx.x;
    int s = bs & (SS - 1);
    int tok = X[bs];
    const float* we = wte + (size_t)tok * DD;
    const float* wp = wpe + (size_t)s * DD;
    float* out = h + (size_t)bs * DD;
    int tid = threadIdx.x;
#pragma unroll
    for (int q = 0; q < 3; q++) {
        int d = tid + q * 256;
        out[d] = we[d] + wp[d];
    }
}

// ---------------- LayerNorm: warp per row, 8 rows per block ----------------
__global__ void __launch_bounds__(256) layernorm_kernel(
        const float* __restrict__ in, const float* __restrict__ g,
        const float* __restrict__ b, __half* __restrict__ out) {
    int warp = threadIdx.x >> 5, lane = threadIdx.x & 31;
    int r = blockIdx.x * 8 + warp;
    const float4* x = (const float4*)(in + (size_t)r * DD);
    float4 v[6];
    float s = 0.0f;
#pragma unroll
    for (int i = 0; i < 6; i++) {
        v[i] = x[lane + 32 * i];
        s += v[i].x + v[i].y + v[i].z + v[i].w;
    }
#pragma unroll
    for (int o = 16; o > 0; o >>= 1) s += __shfl_xor_sync(0xffffffffu, s, o);
    float m = s * (1.0f / DD);
    float vs = 0.0f;
#pragma unroll
    for (int i = 0; i < 6; i++) {
        v[i].x -= m; v[i].y -= m; v[i].z -= m; v[i].w -= m;
        vs += v[i].x * v[i].x + v[i].y * v[i].y + v[i].z * v[i].z + v[i].w * v[i].w;
    }
#pragma unroll
    for (int o = 16; o > 0; o >>= 1) vs += __shfl_xor_sync(0xffffffffu, vs, o);
    float inv = rsqrtf(vs * (1.0f / DD) + 1e-5f);
    const float4* g4 = (const float4*)g;
    const float4* b4 = (const float4*)b;
    uint2* o2 = (uint2*)(out + (size_t)r * DD);
#pragma unroll
    for (int i = 0; i < 6; i++) {
        int idx = lane + 32 * i;
        float4 gg = g4[idx], bb = b4[idx];
        float y0 = v[i].x * inv * gg.x + bb.x;
        float y1 = v[i].y * inv * gg.y + bb.y;
        float y2 = v[i].z * inv * gg.z + bb.z;
        float y3 = v[i].w * inv * gg.w + bb.w;
        o2[idx] = make_uint2(packh2(y0, y1), packh2(y2, y3));
    }
}

// ---------------- FP16 tensor-core GEMM (proven R8) ----------------
template <int EPI, int TM, bool GUARD, typename OutT>
__global__ void __launch_bounds__(256, 2)
h_gemm(const __half* __restrict__ A, const __half* __restrict__ Bt,
       const float* __restrict__ bias, const float* __restrict__ res,
       OutT* __restrict__ C, int M, int N, int K) {
    constexpr int WR = TM / 32;
    constexpr int WC = 8 / WR;
    constexpr int WN = 128 / WC;
    constexpr int NI = WN / 8;
    constexpr int ASTR = TM * 40;
    constexpr int BSTR = 128 * 40;

    extern __shared__ __half smh[];
    __half* Asm = smh;
    __half* Bsm = smh + 3 * ASTR;

    int tid = threadIdx.x;
    int lane = tid & 31;
    int warp = tid >> 5;
    int gid = lane >> 2, tig = lane & 3;
    int warp_m = warp % WR, warp_n = warp / WR;
    int row0 = blockIdx.x * TM, col0 = blockIdx.y * 128;

    int a_r = (lane & 7) + ((lane >> 3) & 1) * 8;
    int a_c = (lane >> 4) * 8;
    int b_n = (lane & 7) + (lane >> 4) * 8;
    int b_k = ((lane >> 3) & 1) * 8;
    uint32_t Au = smem_u32(Asm), Bu = smem_u32(Bsm);

    float acc[2][NI][4];
#pragma unroll
    for (int mi = 0; mi < 2; mi++)
#pragma unroll
        for (int ni = 0; ni < NI; ni++)
#pragma unroll
            for (int e = 0; e < 4; e++) acc[mi][ni][e] = 0.0f;

    auto stage_fn = [&](int s, int k0) {
        __half* As = Asm + s * ASTR;
        __half* Bs = Bsm + s * BSTR;
#pragma unroll
        for (int q = 0; q < TM / 64; q++) {
            int cid = tid + q * 256;
            int r = cid >> 2, ch = (cid & 3) * 8;
            cpa16(As + r * 40 + ch, A + (size_t)(row0 + r) * K + k0 + ch, 16);
        }
#pragma unroll
        for (int q = 0; q < 2; q++) {
            int cid = tid + q * 256;
            int n = cid >> 2, ch = (cid & 3) * 8;
            bool ok = (!GUARD) || (col0 + n) < N;
            const __half* src = ok ? (Bt + (size_t)(col0 + n) * K + k0 + ch) : Bt;
            cpa16(Bs + n * 40 + ch, src, ok ? 16 : 0);
        }
        asm volatile("cp.async.commit_group;\n");
    };

    auto compute_fn = [&](int s) {
        uint32_t Abase = Au + s * (ASTR * 2);
        uint32_t Bbase = Bu + s * (BSTR * 2);
#pragma unroll
        for (int kk = 0; kk < 2; kk++) {
            int kh = kk * 16;
            uint32_t af[2][4];
#pragma unroll
            for (int mi = 0; mi < 2; mi++) {
                int rb = warp_m * 32 + mi * 16;
                ldsm4(af[mi], Abase + ((rb + a_r) * 40 + kh + a_c) * 2);
            }
            uint32_t bf[NI][2];
#pragma unroll
            for (int j = 0; j < NI / 2; j++) {
                uint32_t d[4];
                ldsm4(d, Bbase + ((warp_n * WN + j * 16 + b_n) * 40 + kh + b_k) * 2);
                bf[2 * j][0] = d[0]; bf[2 * j][1] = d[1];
                bf[2 * j + 1][0] = d[2]; bf[2 * j + 1][1] = d[3];
            }
#pragma unroll
            for (int ni = 0; ni < NI; ni++) {
                mma_f16(acc[0][ni], af[0], bf[ni][0], bf[ni][1]);
                mma_f16(acc[1][ni], af[1], bf[ni][0], bf[ni][1]);
            }
        }
    };

    int nIter = K >> 5;
    stage_fn(0, 0);
    stage_fn(1, 32);
    for (int i = 0; i < nIter; i++) {
        asm volatile("cp.async.wait_group 1;\n");
        __syncthreads();
        if (i + 2 < nIter) stage_fn((i + 2) % 3, (i + 2) << 5);
        else asm volatile("cp.async.commit_group;\n");
        compute_fn(i % 3);
    }

    int row_w = row0 + warp_m * 32;
    int col_w = col0 + warp_n * WN;
#pragma unroll
    for (int mi = 0; mi < 2; mi++) {
        int r0 = row_w + mi * 16 + gid;
        int r1 = r0 + 8;
#pragma unroll
        for (int ni = 0; ni < NI; ni++) {
            int c0 = col_w + ni * 8 + tig * 2;
#pragma unroll
            for (int e = 0; e < 4; e++) {
                int r = (e < 2) ? r0 : r1;
                int c = c0 + (e & 1);
                if (GUARD && c >= N) continue;
                float v = acc[mi][ni][e];
                if (EPI == 0) v = v + bias[c];
                if (EPI == 1) v = gelu_f(v + bias[c]);
                if (EPI == 2) v = v + bias[c] + res[(size_t)r * N + c];
                if (sizeof(OutT) == 2)
                    ((__half*)C)[(size_t)r * N + c] = __float2half_rn(v);
                else
                    ((float*)C)[(size_t)r * N + c] = v;
            }
        }
    }
}

#define SMEMH(TM) (3 * ((TM) + 128) * 40 * 2)

// ---------------- FP16 fused flash attention (ldmatrix everywhere) ----------------
// Block = 64 query rows x 1 head; 128 threads = 4 warps, 16 rows/warp.
// Q,K,V all in natural [row][d] XOR-swizzled layout (cp.async loads).
// QK^T: K B-fragments via ldmatrix.x4 ([N,K] storage, proven h_gemm mapping).
// P.V : V B-fragments via ldmatrix.x4.trans ([K,N] storage).
__global__ void __launch_bounds__(128) flash_kernel(const __half* __restrict__ qkv,
                                                    __half* __restrict__ out) {
    int it = blockIdx.x, bh = blockIdx.y;
    int b = bh / HH, h = bh % HH;
    int i0 = it * 64;
    int tid = threadIdx.x, lane = tid & 31, warp = tid >> 5;
    int gid = lane >> 2, tig = lane & 3;

    __shared__ __half Qs[64 * 64];
    __shared__ __half Ks[64 * 64];
    __shared__ __half Vs[64 * 64];

#define SWH(r, c) ((r) * 64 + ((((c) >> 3) ^ ((r) & 7)) * 8) + ((c) & 7))

    // ldmatrix lane-address components (all proven mappings)
    int a_r = (lane & 7) + ((lane >> 3) & 1) * 8;   // A: row within 16-row tile
    int a_c = (lane >> 4) * 8;                      // A: k-half
    int b_n = (lane & 7) + (lane >> 4) * 8;         // B normal: n within 16
    int b_k = ((lane >> 3) & 1) * 8;                // B normal: k-half
    int v_r = (lane & 7) + ((lane >> 3) & 1) * 8;   // B trans: k-row within 16
    int v_c = (lane >> 4) * 8;                      // B trans: n-half
    uint32_t Qu = smem_u32(Qs), Ku = smem_u32(Ks), Vu = smem_u32(Vs);

    // Load Q tile via cp.async
#pragma unroll
    for (int q = 0; q < 4; q++) {
        int cid = tid + q * 128;
        int r = cid >> 3, c8 = (cid & 7) * 8;
        cpa16(&Qs[SWH(r, c8)], qkv + (size_t)(b * SS + i0 + r) * D3 + h * HD + c8, 16);
    }
    asm volatile("cp.async.commit_group;\n");
    asm volatile("cp.async.wait_group 0;\n");
    __syncthreads();

    // Q fragments (4 k16-steps), reused across all j-tiles
    uint32_t qa[4][4];
#pragma unroll
    for (int ks = 0; ks < 4; ks++)
        ldsm4(qa[ks], Qu + SWH(warp * 16 + a_r, ks * 16 + a_c) * 2);

    float oacc[8][4];
#pragma unroll
    for (int nt = 0; nt < 8; nt++)
#pragma unroll
        for (int e = 0; e < 4; e++) oacc[nt][e] = 0.0f;
    float m_run[2] = {-1e30f, -1e30f};
    float l_run[2] = {0.0f, 0.0f};

    for (int j0 = 0; j0 <= i0; j0 += 64) {
        __syncthreads();   // previous iteration's K/V reads done
#pragma unroll
        for (int q = 0; q < 4; q++) {
            int cid = tid + q * 128;
            int r = cid >> 3, c8 = (cid & 7) * 8;
            const __half* kp = qkv + (size_t)(b * SS + j0 + r) * D3 + DD + h * HD + c8;
            cpa16(&Ks[SWH(r, c8)], kp, 16);
            cpa16(&Vs[SWH(r, c8)], kp + DD, 16);
        }
        asm volatile("cp.async.commit_group;\n");
        asm volatile("cp.async.wait_group 0;\n");
        __syncthreads();

        // S = Q K^T
        float sacc[8][4];
#pragma unroll
        for (int nt = 0; nt < 8; nt++)
#pragma unroll
            for (int e = 0; e < 4; e++) sacc[nt][e] = 0.0f;
#pragma unroll
        for (int ks = 0; ks < 4; ks++) {
            int kh = ks * 16;
#pragma unroll
            for (int jt = 0; jt < 4; jt++) {
                uint32_t d[4];
                ldsm4(d, Ku + SWH(jt * 16 + b_n, kh + b_k) * 2);
                mma_f16(sacc[2 * jt],     qa[ks], d[0], d[1]);
                mma_f16(sacc[2 * jt + 1], qa[ks], d[2], d[3]);
            }
        }

        // scale + causal mask (diagonal tile only)
        bool diag = (j0 == i0);
#pragma unroll
        for (int nt = 0; nt < 8; nt++)
#pragma unroll
            for (int e = 0; e < 4; e++) {
                float s = sacc[nt][e] * 0.125f;
                if (diag) {
                    int rr = warp * 16 + gid + (e >> 1) * 8;
                    int cc = nt * 8 + tig * 2 + (e & 1);
                    if (cc > rr) s = -1e10f;
                }
                sacc[nt][e] = s;
            }

        // online softmax (row-half 0: rows gid, 1: rows gid+8)
        float mloc[2] = {-1e30f, -1e30f};
#pragma unroll
        for (int nt = 0; nt < 8; nt++)
#pragma unroll
            for (int e = 0; e < 4; e++) mloc[e >> 1] = fmaxf(mloc[e >> 1], sacc[nt][e]);
#pragma unroll
        for (int hh = 0; hh < 2; hh++) {
            mloc[hh] = fmaxf(mloc[hh], __shfl_xor_sync(0xffffffffu, mloc[hh], 1));
            mloc[hh] = fmaxf(mloc[hh], __shfl_xor_sync(0xffffffffu, mloc[hh], 2));
        }
        float mnew[2] = {fmaxf(m_run[0], mloc[0]), fmaxf(m_run[1], mloc[1])};
        float al[2] = {__expf(m_run[0] - mnew[0]), __expf(m_run[1] - mnew[1])};

        float psum[2] = {0.0f, 0.0f};
#pragma unroll
        for (int nt = 0; nt < 8; nt++)
#pragma unroll
            for (int e = 0; e < 4; e++) {
                float p = __expf(sacc[nt][e] - mnew[e >> 1]);
                sacc[nt][e] = p;
                psum[e >> 1] += p;
            }
#pragma unroll
        for (int hh = 0; hh < 2; hh++) {
            psum[hh] += __shfl_xor_sync(0xffffffffu, psum[hh], 1);
            psum[hh] += __shfl_xor_sync(0xffffffffu, psum[hh], 2);
            l_run[hh] = l_run[hh] * al[hh] + psum[hh];
            m_run[hh] = mnew[hh];
        }
#pragma unroll
        for (int nt = 0; nt < 8; nt++)
#pragma unroll
            for (int e = 0; e < 4; e++) oacc[nt][e] *= al[e >> 1];

        // O += P V : pa from sacc (no shuffles), V fragments via ldsm trans
#pragma unroll
        for (int ks = 0; ks < 4; ks++) {
            uint32_t pa[4];
            pa[0] = packh2(sacc[2 * ks][0],     sacc[2 * ks][1]);
            pa[1] = packh2(sacc[2 * ks][2],     sacc[2 * ks][3]);
            pa[2] = packh2(sacc[2 * ks + 1][0], sacc[2 * ks + 1][1]);
            pa[3] = packh2(sacc[2 * ks + 1][2], sacc[2 * ks + 1][3]);
            int kh = ks * 16;
#pragma unroll
            for (int jt = 0; jt < 4; jt++) {
                uint32_t d[4];
                ldsm4t(d, Vu + SWH(kh + v_r, jt * 16 + v_c) * 2);
                mma_f16(oacc[2 * jt],     pa, d[0], d[1]);
                mma_f16(oacc[2 * jt + 1], pa, d[2], d[3]);
            }
        }
    }

    float inv[2] = {1.0f / l_run[0], 1.0f / l_run[1]};
#pragma unroll
    for (int nt = 0; nt < 8; nt++)
#pragma unroll
        for (int e = 0; e < 4; e++) {
            int i = i0 + warp * 16 + gid + (e >> 1) * 8;
            int d = nt * 8 + tig * 2 + (e & 1);
            float v = oacc[nt][e] * inv[e >> 1];
            out[(size_t)(b * SS + i) * DD + h * HD + d] = __float2half_rn(v);
        }
#undef SWH
}

// ---------------- Orchestration ----------------
extern "C" void kernel_launch(void* const* d_in, const int* in_sizes, int n_in,
                              void* d_out, int out_size) {
    const int*   X      = (const int*)d_in[0];
    const float* wte    = (const float*)d_in[1];
    const float* wpe    = (const float*)d_in[2];
    const float* ln1_g  = (const float*)d_in[3];
    const float* ln1_b  = (const float*)d_in[4];
    const float* attn_w = (const float*)d_in[5];
    const float* attn_b = (const float*)d_in[6];
    const float* proj_w = (const float*)d_in[7];
    const float* proj_b = (const float*)d_in[8];
    const float* ln2_g  = (const float*)d_in[9];
    const float* ln2_b  = (const float*)d_in[10];
    const float* fc_w   = (const float*)d_in[11];
    const float* fc_b   = (const float*)d_in[12];
    const float* fc2_w  = (const float*)d_in[13];
    const float* fc2_b  = (const float*)d_in[14];
    const float* lnf_g  = (const float*)d_in[15];
    const float* lnf_b  = (const float*)d_in[16];
    float* out = (float*)d_out;

    float* h;
    __half *xln, *qkv, *abuf, *fcb, *wh;
    cudaGetSymbolAddress((void**)&h,    g_h);
    cudaGetSymbolAddress((void**)&xln,  g_xln);
    cudaGetSymbolAddress((void**)&qkv,  g_qkv);
    cudaGetSymbolAddress((void**)&abuf, g_abuf);
    cudaGetSymbolAddress((void**)&fcb,  g_fc);
    cudaGetSymbolAddress((void**)&wh,   g_wh);

    cudaFuncSetAttribute(h_gemm<0, 128, false, __half>,
                         cudaFuncAttributeMaxDynamicSharedMemorySize, SMEMH(128));
    cudaFuncSetAttribute(h_gemm<1, 128, false, __half>,
                         cudaFuncAttributeMaxDynamicSharedMemorySize, SMEMH(128));
    cudaFuncSetAttribute(h_gemm<2, 64, false, float>,
                         cudaFuncAttributeMaxDynamicSharedMemorySize, SMEMH(64));
    cudaFuncSetAttribute(h_gemm<3, 128, true, float>,
                         cudaFuncAttributeMaxDynamicSharedMemorySize, SMEMH(128));

    trph_kernel<<<dim3(D3 / 32, DD / 32, LL), dim3(32, 8)>>>(attn_w, wh + OFF_ATTN, DD, D3);
    trph_kernel<<<dim3(DD / 32, DD / 32, LL), dim3(32, 8)>>>(proj_w, wh + OFF_PROJ, DD, DD);
    trph_kernel<<<dim3(D4 / 32, DD / 32, LL), dim3(32, 8)>>>(fc_w,   wh + OFF_FC,   DD, D4);
    trph_kernel<<<dim3(DD / 32, D4 / 32, LL), dim3(32, 8)>>>(fc2_w,  wh + OFF_FC2,  D4, DD);
    convh_kernel<<<4096, 256>>>(wte, wh + OFF_WTE, N_WTE / 4);

    embed_kernel<<<BSr, 256>>>(X, wte, wpe, h);

    for (int l = 0; l < LL; l++) {
        layernorm_kernel<<<BSr / 8, 256>>>(h, ln1_g + l * DD, ln1_b + l * DD, xln);
        h_gemm<0, 128, false, __half>
            <<<dim3(BSr / 128, D3 / 128), 256, SMEMH(128)>>>(
            xln, wh + OFF_ATTN + (size_t)l * DD * D3, attn_b + (size_t)l * D3, nullptr,
            qkv, BSr, D3, DD);
        flash_kernel<<<dim3(SS / 64, BH), 128>>>(qkv, abuf);
        h_gemm<2, 64, false, float>
            <<<dim3(BSr / 64, DD / 128), 256, SMEMH(64)>>>(
            abuf, wh + OFF_PROJ + (size_t)l * DD * DD, proj_b + (size_t)l * DD, h,
            h, BSr, DD, DD);
        layernorm_kernel<<<BSr / 8, 256>>>(h, ln2_g + l * DD, ln2_b + l * DD, xln);
        h_gemm<1, 128, false, __half>
            <<<dim3(BSr / 128, D4 / 128), 256, SMEMH(128)>>>(
            xln, wh + OFF_FC + (size_t)l * DD * D4, fc_b + (size_t)l * D4, nullptr,
            fcb, BSr, D4, DD);
        h_gemm<2, 64, false, float>
            <<<dim3(BSr / 64, DD / 128), 256, SMEMH(64)>>>(
            fcb, wh + OFF_FC2 + (size_t)l * D4 * DD, fc2_b + (size_t)l * DD, h,
            h, BSr, DD, D4);
    }

    layernorm_kernel<<<BSr / 8, 256>>>(h, lnf_g, lnf_b, xln);
    // Logits: proven R8 config — 128x128 tiles, grid x = row tiles for wte L2 reuse
    h_gemm<3, 128, true, float>
        <<<dim3(BSr / 128, (VV + 127) / 128), 256, SMEMH(128)>>>(
        xln, wh + OFF_WTE, nullptr, nullptr, out, BSr, VV, DD);
}